// round 9
// baseline (speedup 1.0000x reference)
#include <cuda_runtime.h>
#include <cuda_fp16.h>

#define HH 1024
#define WW 1024
#define NPIX (HH * WW)

// Persistent device-global scratch (no cudaMalloc allowed).
__device__ uint2  g_Ph[NPIX];   // 4 fp16 weights per pixel (up,dn,lf,rt); zeros at seeds
__device__ float2 g_buf[NPIX];  // ping-pong partner of d_out

__global__ __launch_bounds__(256)
void rw_setup_kernel(const float* __restrict__ img,
                     const int* __restrict__ seeds,
                     float2* __restrict__ x0)
{
    int j = blockIdx.x * 32 + threadIdx.x;
    int i = blockIdx.y * blockDim.y + threadIdx.y;
    int idx = i * WW + j;

    float c  = img[idx];
    bool  cb = (c > 0.1f);

    const int di[4] = {-1, 1, 0, 0};
    const int dj[4] = { 0, 0,-1, 1};

    float w[4];
    float rowsum = 0.0f;
#pragma unroll
    for (int d = 0; d < 4; d++) {
        int ni = i + di[d], nj = j + dj[d];
        bool valid = (ni >= 0) && (ni < HH) && (nj >= 0) && (nj < WW);
        int nidx = (valid ? ni : i) * WW + (valid ? nj : j);
        float nb = img[nidx];
        float same = ((nb > 0.1f) != cb) ? 1.0f : 0.0f;
        float diff = c - nb + same;
        float wt = valid ? expf(-1.0f - fabsf(diff)) : 0.0f;
        w[d] = wt;
        rowsum += wt;
    }
    float inv = 1.0f / rowsum;

    int s = seeds[idx];
    uint2 ph = make_uint2(0u, 0u);
    if (!s) {
        __half2 h01 = __floats2half2_rn(w[0] * inv, w[1] * inv);
        __half2 h23 = __floats2half2_rn(w[2] * inv, w[3] * inv);
        ph.x = *reinterpret_cast<unsigned*>(&h01);
        ph.y = *reinterpret_cast<unsigned*>(&h23);
    }
    g_Ph[idx] = ph;

    float2 x;
    x.x = (s == 1) ? 1.0f : 0.0f;
    x.y = (s == 2) ? 1.0f : 0.0f;
    x0[idx] = x;
}

// ---------------------------------------------------------------------------
// Four Jacobi steps per launch. Horizontal-pair threads (2 px/thread):
// up/dn/ct loaded as aligned float4, P pair as one 16B load (fp16 weights).
// Buffer origins parity-tuned so every READER's pair columns hit even array
// indices (aligned LDS.128); misaligned writers use 2x STS.64.
//   sA: rows -3..34 stride 40, array col0 = logical col -4  (log even->even)
//   sB: rows -2..33 stride 38, array col0 = logical col -3  (log odd ->even)
//   p0: global->sA  (rows 38, pairs even cols -4..34)
//   p1: sA->sB      (rows 36, pairs even cols -2..32)
//   p2: sB->sA      (rows 34, pairs odd  cols -1..31)
//   p3: sA->global  (rows 32, pairs even cols  0..30)
// ---------------------------------------------------------------------------
#define TX 32
#define TY 32
#define SAW 40
#define SBW 38

// One sub-step. RR: row radius. CP0/NPC: first pair col / #pair cols.
// SI/SO: in/out strides. PAL: P pair load 16B-aligned. OAL: output pair
// aligned. GUARD: P (and global-x) loads may leave the image. GIN: input is
// global memory.
template<int RR, int CP0, int NPC, int SI, int SO,
         bool PAL, bool OAL, bool GUARD, bool GIN>
__device__ __forceinline__
void hphase(int tid, int by, int bx,
            const float2* __restrict__ in_log,
            float2* __restrict__ out_log)
{
    constexpr int RN    = 32 + 2 * RR;
    constexpr int TOT   = RN * NPC;
    constexpr int NITER = (TOT + 255) / 256;
    constexpr bool EXACT = (NITER * 256 == TOT);

#pragma unroll 1
    for (int it = 0; it < NITER; it++) {
        int e = tid + it * 256;
        if (EXACT || e < TOT) {
            int row = e / NPC;
            int pc  = e - row * NPC;
            int ro  = row - RR;
            int co  = CP0 + 2 * pc;

            // ---- P pair (fp16 x4 per px) ----
            const uint2* pp = g_Ph + (by + ro) * WW + (bx + co);
            uint2 pr0, pr1;
            if (GUARD) {
                bool vy = (unsigned)(by + ro) < HH;
                pr0 = (vy && (unsigned)(bx + co)     < WW) ? pp[0] : make_uint2(0u, 0u);
                pr1 = (vy && (unsigned)(bx + co + 1) < WW) ? pp[1] : make_uint2(0u, 0u);
            } else if (PAL) {
                uint4 praw = *reinterpret_cast<const uint4*>(pp);
                pr0 = make_uint2(praw.x, praw.y);
                pr1 = make_uint2(praw.z, praw.w);
            } else {
                pr0 = pp[0];
                pr1 = pp[1];
            }
            float2 a01 = __half22float2(*reinterpret_cast<__half2*>(&pr0.x));
            float2 a23 = __half22float2(*reinterpret_cast<__half2*>(&pr0.y));
            float2 b01 = __half22float2(*reinterpret_cast<__half2*>(&pr1.x));
            float2 b23 = __half22float2(*reinterpret_cast<__half2*>(&pr1.y));

            // ---- x loads: up/dn/ct pairs (float4) + lf/rt (float2) ----
            const float2* ip = in_log + ro * SI + co;
            float4 up, dn, ct;
            float2 lf, rt;
            if (GIN && GUARD) {
                bool vym = (unsigned)(by + ro - 1) < HH;
                bool vy0 = (unsigned)(by + ro)     < HH;
                bool vyp = (unsigned)(by + ro + 1) < HH;
                bool vc0 = (unsigned)(bx + co)     < WW;
                bool vc1 = (unsigned)(bx + co + 1) < WW;
                bool vcl = (unsigned)(bx + co - 1) < WW;
                bool vcr = (unsigned)(bx + co + 2) < WW;
                const float2 z = make_float2(0.f, 0.f);
                float2 u0 = (vym && vc0) ? ip[-SI]     : z;
                float2 u1 = (vym && vc1) ? ip[-SI + 1] : z;
                float2 d0 = (vyp && vc0) ? ip[ SI]     : z;
                float2 d1 = (vyp && vc1) ? ip[ SI + 1] : z;
                float2 c0 = (vy0 && vc0) ? ip[0]       : z;
                float2 c1 = (vy0 && vc1) ? ip[1]       : z;
                lf = (vy0 && vcl) ? ip[-1] : z;
                rt = (vy0 && vcr) ? ip[ 2] : z;
                up = make_float4(u0.x, u0.y, u1.x, u1.y);
                dn = make_float4(d0.x, d0.y, d1.x, d1.y);
                ct = make_float4(c0.x, c0.y, c1.x, c1.y);
            } else {
                up = *reinterpret_cast<const float4*>(ip - SI);
                dn = *reinterpret_cast<const float4*>(ip + SI);
                ct = *reinterpret_cast<const float4*>(ip);
                lf = ip[-1];
                rt = ip[2];
            }

            float s0 = 1.0f - ((a01.x + a01.y) + (a23.x + a23.y));
            float s1 = 1.0f - ((b01.x + b01.y) + (b23.x + b23.y));
            float2 o0, o1;
            o0.x = a01.x*up.x + a01.y*dn.x + a23.x*lf.x + a23.y*ct.z + s0*ct.x;
            o0.y = a01.x*up.y + a01.y*dn.y + a23.x*lf.y + a23.y*ct.w + s0*ct.y;
            o1.x = b01.x*up.z + b01.y*dn.z + b23.x*ct.x + b23.y*rt.x + s1*ct.z;
            o1.y = b01.x*up.w + b01.y*dn.w + b23.x*ct.y + b23.y*rt.y + s1*ct.w;

            float2* op = out_log + ro * SO + co;
            if (OAL) {
                *reinterpret_cast<float4*>(op) = make_float4(o0.x, o0.y, o1.x, o1.y);
            } else {
                op[0] = o0;
                op[1] = o1;
            }
        }
    }
}

template<bool GUARD>
__device__ __forceinline__
void rw_body(int tid, int by, int bx,
             const float2* __restrict__ xin, float2* __restrict__ xout,
             float2* __restrict__ sAl, float2* __restrict__ sBl)
{
    const float2* gin  = xin  + by * WW + bx;
    float2*       gout = xout + by * WW + bx;

    //            RR  CP0 NPC  SI   SO   PAL    OAL    GUARD  GIN
    hphase<3, -4, 20, WW,  SAW, true,  true,  GUARD, true >(tid, by, bx, gin, sAl);
    __syncthreads();
    hphase<2, -2, 18, SAW, SBW, true,  false, GUARD, false>(tid, by, bx, sAl, sBl);
    __syncthreads();
    hphase<1, -1, 17, SBW, SAW, false, false, GUARD, false>(tid, by, bx, sBl, sAl);
    __syncthreads();
    // final 32x32 tile is fully in-image -> never guarded
    hphase<0,  0, 16, SAW, WW,  true,  true,  false, false>(tid, by, bx, sAl, gout);
}

__global__ __launch_bounds__(256, 7)
void rw_step4_kernel(const float2* __restrict__ xin,
                     float2* __restrict__ xout)
{
    __shared__ alignas(16) float2 sA[38 * SAW];  // 12.2 KB
    __shared__ alignas(16) float2 sB[36 * SBW];  // 10.9 KB

    const int tid = threadIdx.x;
    const int bx  = blockIdx.x * TX;
    const int by  = blockIdx.y * TY;

    float2* sAl = sA + 3 * SAW + 4;  // logical (by, bx); log col -4 = array 0
    float2* sBl = sB + 2 * SBW + 3;  // log col -3 = array 0

    // p0 touches x rows by-4..by+35, cols bx-5..bx+36
    const bool interior = (bx >= 8) && (bx + 37 <= WW) &&
                          (by >= 4) && (by + 36 <= HH);
    if (interior) rw_body<false>(tid, by, bx, xin, xout, sAl, sBl);
    else          rw_body<true >(tid, by, bx, xin, xout, sAl, sBl);
}

extern "C" void kernel_launch(void* const* d_in, const int* in_sizes, int n_in,
                              void* d_out, int out_size)
{
    const float* img   = (const float*)d_in[0];
    const int*   seeds = (const int*)d_in[1];
    float2*      A     = (float2*)d_out;

    float2* B = nullptr;
    cudaGetSymbolAddress((void**)&B, g_buf);

    {
        dim3 blk(32, 8);
        dim3 grd(WW / 32, HH / 8);
        // x0 written into B; 25 quad-step kernels alternate B->A->B...,
        // t=24 (even) writes A = d_out.
        rw_setup_kernel<<<grd, blk>>>(img, seeds, B);
    }

    dim3 blk(256);
    dim3 grd(WW / TX, HH / TY);
    for (int t = 0; t < 25; t++) {
        const float2* xin  = (t & 1) ? A : B;
        float2*       xout = (t & 1) ? B : A;
        rw_step4_kernel<<<grd, blk>>>(xin, xout);
    }
}

// round 10
// speedup vs baseline: 1.2752x; 1.2752x over previous
#include <cuda_runtime.h>
#include <cuda_fp16.h>

#define HH 1024
#define WW 1024
#define NPIX (HH * WW)

// Persistent device-global scratch (no cudaMalloc allowed).
__device__ uint2  g_Ph[NPIX];   // 4 fp16 weights (up,dn,lf,rt) per pixel; zeros at seeds
__device__ float2 g_buf[NPIX];  // ping-pong partner of d_out

__global__ __launch_bounds__(256)
void rw_setup_kernel(const float* __restrict__ img,
                     const int* __restrict__ seeds,
                     float2* __restrict__ x0)
{
    int j = blockIdx.x * 32 + threadIdx.x;
    int i = blockIdx.y * blockDim.y + threadIdx.y;
    int idx = i * WW + j;

    float c  = img[idx];
    bool  cb = (c > 0.1f);

    const int di[4] = {-1, 1, 0, 0};
    const int dj[4] = { 0, 0,-1, 1};

    float w[4];
    float rowsum = 0.0f;
#pragma unroll
    for (int d = 0; d < 4; d++) {
        int ni = i + di[d], nj = j + dj[d];
        bool valid = (ni >= 0) && (ni < HH) && (nj >= 0) && (nj < WW);
        int nidx = (valid ? ni : i) * WW + (valid ? nj : j);
        float nb = img[nidx];
        float same = ((nb > 0.1f) != cb) ? 1.0f : 0.0f;
        float diff = c - nb + same;
        float wt = valid ? expf(-1.0f - fabsf(diff)) : 0.0f;
        w[d] = wt;
        rowsum += wt;
    }
    float inv = 1.0f / rowsum;

    int s = seeds[idx];
    uint2 ph = make_uint2(0u, 0u);
    if (!s) {
        __half2 h01 = __floats2half2_rn(w[0] * inv, w[1] * inv);
        __half2 h23 = __floats2half2_rn(w[2] * inv, w[3] * inv);
        ph.x = *reinterpret_cast<unsigned*>(&h01);
        ph.y = *reinterpret_cast<unsigned*>(&h23);
    }
    g_Ph[idx] = ph;

    float2 x;
    x.x = (s == 1) ? 1.0f : 0.0f;
    x.y = (s == 2) ? 1.0f : 0.0f;
    x0[idx] = x;
}

// ---------------------------------------------------------------------------
// Four Jacobi steps per launch. Vertical-pair threads (2 px/thread, shared
// 4-row center column -> 8 LDS per 2 px). Phase 0 reads x straight from
// global. P in fp16 (uint2 per px) from L2, converted to fp32 in regs;
// self coefficient computed in fp32 -> rows exactly stochastic.
//   sA: 38x38 logical origin (by-3, bx-3)   sB: 36x36 origin (by-2, bx-2)
//   p0: global->sA (R=3)  p1: sA->sB (R=2)  p2: sB->sA (R=1)  p3: sA->global
// ---------------------------------------------------------------------------
#define TX 32
#define TY 32
#define SA 38
#define SB 36

__device__ __forceinline__
void unpack_p(uint2 ph, float2& w01, float2& w23)
{
    w01 = __half22float2(*reinterpret_cast<__half2*>(&ph.x));
    w23 = __half22float2(*reinterpret_cast<__half2*>(&ph.y));
}

// One Jacobi sub-step over a DxD output region, 2 vertically-adjacent px per
// thread. in_log/out_log point at logical pixel (by, bx) of their buffers.
//  D:  region side (even)   R: region radius (logical rows/cols in [-R, D-R))
//  SI/SO: input/output strides   GUARD: coords may leave the image
//  GIN: input is global memory (x reads guarded when GUARD)
template<int D, int R, int SI, int SO, bool GUARD, bool GIN>
__device__ __forceinline__
void pair_phase(int tid, int by, int bx,
                const float2* __restrict__ in_log,
                float2* __restrict__ out_log)
{
    constexpr int TOT   = D * (D / 2);
    constexpr int NITER = (TOT + 255) / 256;
    constexpr bool EXACT = (NITER * 256 == TOT);

    for (int it = 0; it < NITER; it++) {
        int e = tid + it * 256;
        if (EXACT || e < TOT) {
            int pr = e / D;
            int cc = e - pr * D;
            int ro = 2 * pr - R;   // logical row of first output px
            int co = cc - R;       // logical col

            // --- P loads first (deep MLP; L2-resident, fp16) ---
            const uint2* pp = g_Ph + (by + ro) * WW + (bx + co);
            uint2 ph1, ph2;
            if (GUARD) {
                bool vc = (unsigned)(bx + co) < WW;
                ph1 = (vc && (unsigned)(by + ro)     < HH) ? pp[0]  : make_uint2(0u, 0u);
                ph2 = (vc && (unsigned)(by + ro + 1) < HH) ? pp[WW] : make_uint2(0u, 0u);
            } else {
                ph1 = pp[0];
                ph2 = pp[WW];
            }

            // --- x reads: 4-row center column + lf/rt for both rows ---
            const float2* ip = in_log + ro * SI + co;
            float2 a, b, c, d, lf0, rt0, lf1, rt1;
            if (GIN && GUARD) {
                bool vc  = (unsigned)(bx + co)     < WW;
                bool vcl = (unsigned)(bx + co - 1) < WW;
                bool vcr = (unsigned)(bx + co + 1) < WW;
                bool vym = (unsigned)(by + ro - 1) < HH;
                bool vy0 = (unsigned)(by + ro)     < HH;
                bool vy1 = (unsigned)(by + ro + 1) < HH;
                bool vy2 = (unsigned)(by + ro + 2) < HH;
                const float2 z = make_float2(0.f, 0.f);
                a   = (vym && vc ) ? ip[-SI]     : z;
                b   = (vy0 && vc ) ? ip[0]       : z;
                c   = (vy1 && vc ) ? ip[SI]      : z;
                d   = (vy2 && vc ) ? ip[2 * SI]  : z;
                lf0 = (vy0 && vcl) ? ip[-1]      : z;
                rt0 = (vy0 && vcr) ? ip[1]       : z;
                lf1 = (vy1 && vcl) ? ip[SI - 1]  : z;
                rt1 = (vy1 && vcr) ? ip[SI + 1]  : z;
            } else {
                a   = ip[-SI];
                b   = ip[0];
                c   = ip[SI];
                d   = ip[2 * SI];
                lf0 = ip[-1];
                rt0 = ip[1];
                lf1 = ip[SI - 1];
                rt1 = ip[SI + 1];
            }

            float2 p1a, p1b, p2a, p2b;
            unpack_p(ph1, p1a, p1b);   // p1a=(up,dn) p1b=(lf,rt)
            unpack_p(ph2, p2a, p2b);

            float s1 = 1.0f - ((p1a.x + p1a.y) + (p1b.x + p1b.y));
            float s2 = 1.0f - ((p2a.x + p2a.y) + (p2b.x + p2b.y));
            float2 o0, o1;
            o0.x = p1a.x*a.x + p1a.y*c.x + p1b.x*lf0.x + p1b.y*rt0.x + s1*b.x;
            o0.y = p1a.x*a.y + p1a.y*c.y + p1b.x*lf0.y + p1b.y*rt0.y + s1*b.y;
            o1.x = p2a.x*b.x + p2a.y*d.x + p2b.x*lf1.x + p2b.y*rt1.x + s2*c.x;
            o1.y = p2a.x*b.y + p2a.y*d.y + p2b.x*lf1.y + p2b.y*rt1.y + s2*c.y;

            out_log[ro * SO + co]       = o0;
            out_log[(ro + 1) * SO + co] = o1;
        }
    }
}

template<bool GUARD>
__device__ __forceinline__
void rw_body(int tid, int by, int bx,
             const float2* __restrict__ xin, float2* __restrict__ xout,
             float2* __restrict__ sAl, float2* __restrict__ sBl)
{
    const float2* gin  = xin  + by * WW + bx;
    float2*       gout = xout + by * WW + bx;

    pair_phase<38, 3, WW, SA, GUARD, true >(tid, by, bx, gin, sAl);   // global -> sA
    __syncthreads();
    pair_phase<36, 2, SA, SB, GUARD, false>(tid, by, bx, sAl, sBl);   // sA -> sB
    __syncthreads();
    pair_phase<34, 1, SB, SA, GUARD, false>(tid, by, bx, sBl, sAl);   // sB -> sA
    __syncthreads();
    // final tile is fully in-image -> never guarded
    pair_phase<32, 0, SA, WW, false, false>(tid, by, bx, sAl, gout);  // sA -> global
}

__global__ __launch_bounds__(256, 7)
void rw_step4_kernel(const float2* __restrict__ xin,
                     float2* __restrict__ xout)
{
    __shared__ float2 sA[SA * SA];  // 11.55 KB
    __shared__ float2 sB[SB * SB];  // 10.4 KB

    const int tid = threadIdx.x;
    const int bx  = blockIdx.x * TX;
    const int by  = blockIdx.y * TY;

    float2* sAl = sA + 3 * SA + 3;  // logical (by, bx)
    float2* sBl = sB + 2 * SB + 2;

    const bool interior = (bx >= 4) && (bx + 36 <= WW) &&
                          (by >= 4) && (by + 36 <= HH);
    if (interior) rw_body<false>(tid, by, bx, xin, xout, sAl, sBl);
    else          rw_body<true >(tid, by, bx, xin, xout, sAl, sBl);
}

extern "C" void kernel_launch(void* const* d_in, const int* in_sizes, int n_in,
                              void* d_out, int out_size)
{
    const float* img   = (const float*)d_in[0];
    const int*   seeds = (const int*)d_in[1];
    float2*      A     = (float2*)d_out;

    float2* B = nullptr;
    cudaGetSymbolAddress((void**)&B, g_buf);

    {
        dim3 blk(32, 8);
        dim3 grd(WW / 32, HH / 8);
        // x0 written into B; 25 quad-step kernels alternate B->A->B...,
        // t=24 (even) writes A = d_out.
        rw_setup_kernel<<<grd, blk>>>(img, seeds, B);
    }

    dim3 blk(256);
    dim3 grd(WW / TX, HH / TY);
    for (int t = 0; t < 25; t++) {
        const float2* xin  = (t & 1) ? A : B;
        float2*       xout = (t & 1) ? B : A;
        rw_step4_kernel<<<grd, blk>>>(xin, xout);
    }
}

// round 11
// speedup vs baseline: 1.2822x; 1.0056x over previous
#include <cuda_runtime.h>
#include <cuda_fp16.h>

#define HH 1024
#define WW 1024
#define NPIX (HH * WW)

// Persistent device-global scratch (no cudaMalloc allowed).
__device__ uint2  g_Ph[NPIX];   // 4 fp16 weights (up,dn,lf,rt) per pixel; zeros at seeds
__device__ float2 g_buf[NPIX];  // ping-pong partner of d_out

__global__ __launch_bounds__(256)
void rw_setup_kernel(const float* __restrict__ img,
                     const int* __restrict__ seeds,
                     float2* __restrict__ x0)
{
    int j = blockIdx.x * 32 + threadIdx.x;
    int i = blockIdx.y * blockDim.y + threadIdx.y;
    int idx = i * WW + j;

    float c  = img[idx];
    bool  cb = (c > 0.1f);

    const int di[4] = {-1, 1, 0, 0};
    const int dj[4] = { 0, 0,-1, 1};

    float w[4];
    float rowsum = 0.0f;
#pragma unroll
    for (int d = 0; d < 4; d++) {
        int ni = i + di[d], nj = j + dj[d];
        bool valid = (ni >= 0) && (ni < HH) && (nj >= 0) && (nj < WW);
        int nidx = (valid ? ni : i) * WW + (valid ? nj : j);
        float nb = img[nidx];
        float same = ((nb > 0.1f) != cb) ? 1.0f : 0.0f;
        float diff = c - nb + same;
        float wt = valid ? expf(-1.0f - fabsf(diff)) : 0.0f;
        w[d] = wt;
        rowsum += wt;
    }
    float inv = 1.0f / rowsum;

    int s = seeds[idx];
    uint2 ph = make_uint2(0u, 0u);
    if (!s) {
        __half2 h01 = __floats2half2_rn(w[0] * inv, w[1] * inv);
        __half2 h23 = __floats2half2_rn(w[2] * inv, w[3] * inv);
        ph.x = *reinterpret_cast<unsigned*>(&h01);
        ph.y = *reinterpret_cast<unsigned*>(&h23);
    }
    g_Ph[idx] = ph;

    float2 x;
    x.x = (s == 1) ? 1.0f : 0.0f;
    x.y = (s == 2) ? 1.0f : 0.0f;
    x0[idx] = x;
}

// ---------------------------------------------------------------------------
// Four Jacobi steps per launch. Vertical-pair threads (2 px/thread, shared
// 4-row center column -> 8 LDS per 2 px). Phase 0 reads x straight from
// global. P in fp16 (uint2 per px) from L2, converted to fp32 in regs;
// self coefficient computed in fp32 -> rows exactly stochastic.
// 8 blocks/SM (2048 threads, 176 KB smem, 32 regs) -> max occupancy,
// still a single wave (148*8 = 1184 >= 1024 blocks).
//   sA: 38x38 logical origin (by-3, bx-3)   sB: 36x36 origin (by-2, bx-2)
//   p0: global->sA (R=3)  p1: sA->sB (R=2)  p2: sB->sA (R=1)  p3: sA->global
// ---------------------------------------------------------------------------
#define TX 32
#define TY 32
#define SA 38
#define SB 36

__device__ __forceinline__
void unpack_p(uint2 ph, float2& w01, float2& w23)
{
    w01 = __half22float2(*reinterpret_cast<__half2*>(&ph.x));
    w23 = __half22float2(*reinterpret_cast<__half2*>(&ph.y));
}

// One Jacobi sub-step over a DxD output region, 2 vertically-adjacent px per
// thread. in_log/out_log point at logical pixel (by, bx) of their buffers.
//  D:  region side (even)   R: region radius (logical rows/cols in [-R, D-R))
//  SI/SO: input/output strides   GUARD: coords may leave the image
//  GIN: input is global memory (x reads guarded when GUARD)
template<int D, int R, int SI, int SO, bool GUARD, bool GIN>
__device__ __forceinline__
void pair_phase(int tid, int by, int bx,
                const float2* __restrict__ in_log,
                float2* __restrict__ out_log)
{
    constexpr int TOT   = D * (D / 2);
    constexpr int NITER = (TOT + 255) / 256;
    constexpr bool EXACT = (NITER * 256 == TOT);

    for (int it = 0; it < NITER; it++) {
        int e = tid + it * 256;
        if (EXACT || e < TOT) {
            int pr = e / D;
            int cc = e - pr * D;
            int ro = 2 * pr - R;   // logical row of first output px
            int co = cc - R;       // logical col

            // --- P loads first (deep MLP; L2-resident, fp16) ---
            const uint2* pp = g_Ph + (by + ro) * WW + (bx + co);
            uint2 ph1, ph2;
            if (GUARD) {
                bool vc = (unsigned)(bx + co) < WW;
                ph1 = (vc && (unsigned)(by + ro)     < HH) ? pp[0]  : make_uint2(0u, 0u);
                ph2 = (vc && (unsigned)(by + ro + 1) < HH) ? pp[WW] : make_uint2(0u, 0u);
            } else {
                ph1 = pp[0];
                ph2 = pp[WW];
            }

            // --- x reads: 4-row center column + lf/rt for both rows ---
            const float2* ip = in_log + ro * SI + co;
            float2 a, b, c, d, lf0, rt0, lf1, rt1;
            if (GIN && GUARD) {
                bool vc  = (unsigned)(bx + co)     < WW;
                bool vcl = (unsigned)(bx + co - 1) < WW;
                bool vcr = (unsigned)(bx + co + 1) < WW;
                bool vym = (unsigned)(by + ro - 1) < HH;
                bool vy0 = (unsigned)(by + ro)     < HH;
                bool vy1 = (unsigned)(by + ro + 1) < HH;
                bool vy2 = (unsigned)(by + ro + 2) < HH;
                const float2 z = make_float2(0.f, 0.f);
                a   = (vym && vc ) ? ip[-SI]     : z;
                b   = (vy0 && vc ) ? ip[0]       : z;
                c   = (vy1 && vc ) ? ip[SI]      : z;
                d   = (vy2 && vc ) ? ip[2 * SI]  : z;
                lf0 = (vy0 && vcl) ? ip[-1]      : z;
                rt0 = (vy0 && vcr) ? ip[1]       : z;
                lf1 = (vy1 && vcl) ? ip[SI - 1]  : z;
                rt1 = (vy1 && vcr) ? ip[SI + 1]  : z;
            } else {
                a   = ip[-SI];
                b   = ip[0];
                c   = ip[SI];
                d   = ip[2 * SI];
                lf0 = ip[-1];
                rt0 = ip[1];
                lf1 = ip[SI - 1];
                rt1 = ip[SI + 1];
            }

            float2 p1a, p1b, p2a, p2b;
            unpack_p(ph1, p1a, p1b);   // p1a=(up,dn) p1b=(lf,rt)
            unpack_p(ph2, p2a, p2b);

            float s1 = 1.0f - ((p1a.x + p1a.y) + (p1b.x + p1b.y));
            float s2 = 1.0f - ((p2a.x + p2a.y) + (p2b.x + p2b.y));
            float2 o0, o1;
            o0.x = p1a.x*a.x + p1a.y*c.x + p1b.x*lf0.x + p1b.y*rt0.x + s1*b.x;
            o0.y = p1a.x*a.y + p1a.y*c.y + p1b.x*lf0.y + p1b.y*rt0.y + s1*b.y;
            o1.x = p2a.x*b.x + p2a.y*d.x + p2b.x*lf1.x + p2b.y*rt1.x + s2*c.x;
            o1.y = p2a.x*b.y + p2a.y*d.y + p2b.x*lf1.y + p2b.y*rt1.y + s2*c.y;

            out_log[ro * SO + co]       = o0;
            out_log[(ro + 1) * SO + co] = o1;
        }
    }
}

template<bool GUARD>
__device__ __forceinline__
void rw_body(int tid, int by, int bx,
             const float2* __restrict__ xin, float2* __restrict__ xout,
             float2* __restrict__ sAl, float2* __restrict__ sBl)
{
    const float2* gin  = xin  + by * WW + bx;
    float2*       gout = xout + by * WW + bx;

    pair_phase<38, 3, WW, SA, GUARD, true >(tid, by, bx, gin, sAl);   // global -> sA
    __syncthreads();
    pair_phase<36, 2, SA, SB, GUARD, false>(tid, by, bx, sAl, sBl);   // sA -> sB
    __syncthreads();
    pair_phase<34, 1, SB, SA, GUARD, false>(tid, by, bx, sBl, sAl);   // sB -> sA
    __syncthreads();
    // final tile is fully in-image -> never guarded
    pair_phase<32, 0, SA, WW, false, false>(tid, by, bx, sAl, gout);  // sA -> global
}

__global__ __launch_bounds__(256, 8)
void rw_step4_kernel(const float2* __restrict__ xin,
                     float2* __restrict__ xout)
{
    __shared__ float2 sA[SA * SA];  // 11.55 KB
    __shared__ float2 sB[SB * SB];  // 10.4 KB

    const int tid = threadIdx.x;
    const int bx  = blockIdx.x * TX;
    const int by  = blockIdx.y * TY;

    float2* sAl = sA + 3 * SA + 3;  // logical (by, bx)
    float2* sBl = sB + 2 * SB + 2;

    const bool interior = (bx >= 4) && (bx + 36 <= WW) &&
                          (by >= 4) && (by + 36 <= HH);
    if (interior) rw_body<false>(tid, by, bx, xin, xout, sAl, sBl);
    else          rw_body<true >(tid, by, bx, xin, xout, sAl, sBl);
}

extern "C" void kernel_launch(void* const* d_in, const int* in_sizes, int n_in,
                              void* d_out, int out_size)
{
    const float* img   = (const float*)d_in[0];
    const int*   seeds = (const int*)d_in[1];
    float2*      A     = (float2*)d_out;

    float2* B = nullptr;
    cudaGetSymbolAddress((void**)&B, g_buf);

    {
        dim3 blk(32, 8);
        dim3 grd(WW / 32, HH / 8);
        // x0 written into B; 25 quad-step kernels alternate B->A->B...,
        // t=24 (even) writes A = d_out.
        rw_setup_kernel<<<grd, blk>>>(img, seeds, B);
    }

    dim3 blk(256);
    dim3 grd(WW / TX, HH / TY);
    for (int t = 0; t < 25; t++) {
        const float2* xin  = (t & 1) ? A : B;
        float2*       xout = (t & 1) ? B : A;
        rw_step4_kernel<<<grd, blk>>>(xin, xout);
    }
}